// round 14
// baseline (speedup 1.0000x reference)
#include <cuda_runtime.h>
#include <cuda_fp16.h>
#include <math.h>
#include <cstdint>

#define BB 8
#define SS 1024
#define EE 128
#define HH 16
#define BHN 128
#define FF 6144

#define QPH 136    // pitch (halves) for 128-wide half tiles
#define VPH 40     // pitch (halves) for 32-wide half tiles (V^T)
#define CPIT 132   // pitch (floats) for staging

// Scratch (fp16): q,k in [bh][s][d]; v transposed in [bh][d][s]
__device__ __half g_q [(size_t)BHN*SS*EE];
__device__ __half g_k [(size_t)BHN*SS*EE];
__device__ __half g_vT[(size_t)BHN*EE*SS];
__device__ float  g_cs[SS*64];
__device__ float  g_sn[SS*64];

__device__ __forceinline__ void mma16(float d[4], const uint32_t a[4],
                                      const uint32_t b[2]) {
    asm volatile(
        "mma.sync.aligned.m16n8k16.row.col.f32.f16.f16.f32 "
        "{%0,%1,%2,%3}, {%4,%5,%6,%7}, {%8,%9}, {%0,%1,%2,%3};"
        : "+f"(d[0]), "+f"(d[1]), "+f"(d[2]), "+f"(d[3])
        : "r"(a[0]), "r"(a[1]), "r"(a[2]), "r"(a[3]), "r"(b[0]), "r"(b[1]));
}

__device__ __forceinline__ uint32_t ldh2(const __half* p) {
    return *(const uint32_t*)p;
}

__device__ __forceinline__ uint32_t smem_u32(const void* p) {
    uint32_t a;
    asm("{ .reg .u64 t; cvta.to.shared.u64 t, %1; cvt.u32.u64 %0, t; }"
        : "=r"(a) : "l"(p));
    return a;
}

__device__ __forceinline__ void cpa16(uint32_t dst, const void* src) {
    asm volatile("cp.async.cg.shared.global [%0], [%1], 16;"
                 :: "r"(dst), "l"(src));
}
#define CP_COMMIT() asm volatile("cp.async.commit_group;" ::: "memory")
#define CP_WAIT0()  asm volatile("cp.async.wait_group 0;"  ::: "memory")
#define BAR_HALF(id) asm volatile("bar.sync %0, 256;" :: "r"(id) : "memory")

__device__ __forceinline__ uint4 pack8(float4 x, float4 y) {
    __half2 h0 = __floats2half2_rn(x.x, x.y);
    __half2 h1 = __floats2half2_rn(x.z, x.w);
    __half2 h2 = __floats2half2_rn(y.x, y.y);
    __half2 h3 = __floats2half2_rn(y.z, y.w);
    uint4 u;
    u.x = *(uint32_t*)&h0; u.y = *(uint32_t*)&h1;
    u.z = *(uint32_t*)&h2; u.w = *(uint32_t*)&h3;
    return u;
}

// ===========================================================================
// Kernel 0: RoPE table
// ===========================================================================
__global__ void rope_table_kernel() {
    int idx = blockIdx.x * blockDim.x + threadIdx.x;
    if (idx >= SS * 64) return;
    int s = idx >> 6, j = idx & 63;
    float invf = (float)pow(10000.0, -(double)j / 64.0);
    float ang = (float)s * invf;
    float sn, cs;
    sincosf(ang, &sn, &cs);
    g_cs[idx] = cs;
    g_sn[idx] = sn;
}

// ===========================================================================
// Kernel 1: QKV = X @ W^T + b (fp16 mma), fused RoPE, scatter q/k/vT.
// (unchanged from the 418.9us best)
// ===========================================================================
__global__ void __launch_bounds__(256, 2) qkv_kernel(
    const float* __restrict__ X, const float* __restrict__ W,
    const float* __restrict__ bias)
{
    extern __shared__ char smraw[];
    __half* Ah = (__half*)smraw;            // [128][QPH]
    __half* Bh = Ah + 128 * QPH;            // [128][QPH]
    float*  Cs = (float*)smraw;             // [128][CPIT] (reused after gemm)

    const int tid = threadIdx.x, wid = tid >> 5, lane = tid & 31;
    const int g = lane >> 2, t = lane & 3;
    const int wm = wid & 3, wn = wid >> 2;
    const int nt = blockIdx.x, mt = blockIdx.y;

    const float* Ag = X + (size_t)mt * 128 * EE;
    const float* Bg = W + (size_t)nt * 128 * EE;

#pragma unroll
    for (int i = 0; i < 8; i++) {
        int seg = tid + i * 256;
        int r = seg >> 4, c8 = (seg & 15) << 3;
        float4 a1 = *(const float4*)&Ag[r * EE + c8];
        float4 a2 = *(const float4*)&Ag[r * EE + c8 + 4];
        *(uint4*)&Ah[r * QPH + c8] = pack8(a1, a2);
        float4 b1 = *(const float4*)&Bg[r * EE + c8];
        float4 b2 = *(const float4*)&Bg[r * EE + c8 + 4];
        *(uint4*)&Bh[r * QPH + c8] = pack8(b1, b2);
    }
    __syncthreads();

    float acc[2][8][4];
#pragma unroll
    for (int mi = 0; mi < 2; mi++)
#pragma unroll
        for (int ni = 0; ni < 8; ni++)
#pragma unroll
            for (int ci = 0; ci < 4; ci++) acc[mi][ni][ci] = 0.0f;

    const __half* Ab = Ah + (wm * 32 + g) * QPH + 2 * t;
    const __half* Bb = Bh + (wn * 64 + g) * QPH + 2 * t;

#pragma unroll
    for (int k0 = 0; k0 < 8; k0++) {
        uint32_t af[2][4], bf[8][2];
#pragma unroll
        for (int mi = 0; mi < 2; mi++) {
            const __half* p = Ab + mi * 16 * QPH + k0 * 16;
            af[mi][0] = ldh2(p);
            af[mi][1] = ldh2(p + 8 * QPH);
            af[mi][2] = ldh2(p + 8);
            af[mi][3] = ldh2(p + 8 * QPH + 8);
        }
#pragma unroll
        for (int ni = 0; ni < 8; ni++) {
            const __half* p = Bb + ni * 8 * QPH + k0 * 16;
            bf[ni][0] = ldh2(p);
            bf[ni][1] = ldh2(p + 8);
        }
#pragma unroll
        for (int mi = 0; mi < 2; mi++)
#pragma unroll
            for (int ni = 0; ni < 8; ni++)
                mma16(acc[mi][ni], af[mi], bf[ni]);
    }
    __syncthreads();

#pragma unroll
    for (int mi = 0; mi < 2; mi++)
#pragma unroll
        for (int ni = 0; ni < 8; ni++) {
            int row = wm * 32 + mi * 16 + g;
            int col = wn * 64 + ni * 8 + t * 2;
            *(float2*)&Cs[row * CPIT + col] =
                make_float2(acc[mi][ni][0], acc[mi][ni][1]);
            *(float2*)&Cs[(row + 8) * CPIT + col] =
                make_float2(acc[mi][ni][2], acc[mi][ni][3]);
        }
    __syncthreads();

    const int c = nt >> 4, h = nt & 15;
    const float* bptr = bias + nt * 128;
    const int bidx = (mt * 128) >> 10;
    const int s_base = (mt * 128) & 1023;

    if (c == 2) {
        size_t vb = ((size_t)(bidx * HH + h)) * EE * SS;
#pragma unroll
        for (int it = 0; it < 16; it++) {
            int d = it * 8 + wid;
            float bd = bptr[d];
#pragma unroll
            for (int q = 0; q < 4; q++) {
                int r = q * 32 + lane;
                g_vT[vb + (size_t)d * SS + s_base + r] =
                    __float2half_rn(Cs[r * CPIT + d] + bd);
            }
        }
    } else {
        __half* dst = (c == 0) ? g_q : g_k;
        const int row = tid >> 1, part = tid & 1;
        const int s = s_base + row;
        size_t rb = (((size_t)(bidx * HH + h)) * SS + s) * EE;
#pragma unroll
        for (int jq = 0; jq < 8; jq++) {
            int j = part * 32 + jq * 4;
            float4 x1 = *(float4*)&Cs[row * CPIT + j];
            float4 x2 = *(float4*)&Cs[row * CPIT + 64 + j];
            float4 b1 = *(const float4*)&bptr[j];
            float4 b2 = *(const float4*)&bptr[64 + j];
            float4 cs4 = *(const float4*)&g_cs[s * 64 + j];
            float4 sn4 = *(const float4*)&g_sn[s * 64 + j];
            x1.x += b1.x; x1.y += b1.y; x1.z += b1.z; x1.w += b1.w;
            x2.x += b2.x; x2.y += b2.y; x2.z += b2.z; x2.w += b2.w;
            __half2 o1a = __floats2half2_rn(x1.x * cs4.x - x2.x * sn4.x,
                                            x1.y * cs4.y - x2.y * sn4.y);
            __half2 o1b = __floats2half2_rn(x1.z * cs4.z - x2.z * sn4.z,
                                            x1.w * cs4.w - x2.w * sn4.w);
            __half2 o2a = __floats2half2_rn(x1.x * sn4.x + x2.x * cs4.x,
                                            x1.y * sn4.y + x2.y * cs4.y);
            __half2 o2b = __floats2half2_rn(x1.z * sn4.z + x2.z * cs4.z,
                                            x1.w * sn4.w + x2.w * cs4.w);
            uint2 u1 = make_uint2(*(uint32_t*)&o1a, *(uint32_t*)&o1b);
            uint2 u2 = make_uint2(*(uint32_t*)&o2a, *(uint32_t*)&o2b);
            *(uint2*)&dst[rb + j]      = u1;
            *(uint2*)&dst[rb + 64 + j] = u2;
        }
    }
}

// ===========================================================================
// Kernel 2: attention. 512-thread CTA = 128 q rows of one (b,h), split into
// TWO INDEPENDENT 256-thread halves: half h owns keys [512h, 512h+512) with
// its own K/V double-buffers and its own named barrier (bar 1+h) -> the two
// halves drift like R11's two co-resident CTAs. Per half: the proven R11
// loop (16 iters of 32 keys, register-P FA2, cp.async). Grid 1024 @ 1 CTA/SM
// (reg-limited) -> 6.92->7 waves (was 3.46->4): quantization 15.6% -> 1.2%.
// K/V traffic per CTA unchanged. Final in-smem combine of the two halves.
// ===========================================================================
#define AQ_OFF   0
#define AK_OFF   34816                        // per half: +h*17408 (2 x 8704)
#define AV_OFF   (34816 + 2*17408)            // per half: +h*20480 (2 x 10240)
#define ATTN_SMEM (AV_OFF + 2*20480)          // 110592

__global__ void __launch_bounds__(512, 1) attn_kernel(float* __restrict__ out)
{
    extern __shared__ char smraw[];
    __half* Qs = (__half*)(smraw + AQ_OFF);
    const uint32_t sb = smem_u32(smraw);

    const int tid = threadIdx.x, wid = tid >> 5, lane = tid & 31;
    const int g = lane >> 2, t = lane & 3;
    const int half = wid >> 3, hw = wid & 7;      // half 0/1, warp-in-half 0..7
    const int htid = tid & 255;
    const int qt = blockIdx.x, bh = blockIdx.y;

    const __half* qg = g_q  + (size_t)bh * SS * EE + (size_t)qt * 128 * EE;
    const __half* kg = g_k  + (size_t)bh * SS * EE + (size_t)half * 512 * EE;
    const __half* vg = g_vT + (size_t)bh * EE * SS + half * 512;

    const uint32_t AKh = AK_OFF + half * 17408;
    const uint32_t AVh = AV_OFF + half * 20480;
    __half* Ksh = (__half*)(smraw + AKh);
    __half* Vsh = (__half*)(smraw + AVh);

    // cp.async segments (per half): K tile 32x128h = 512 16B chunks; V same.
    const int ks0 = htid,      ks1 = htid + 256;
    const int kr0 = ks0 >> 4,  kc0 = (ks0 & 15) << 3;
    const int kr1 = ks1 >> 4,  kc1 = (ks1 & 15) << 3;
    const int vr0 = ks0 >> 2,  vc0 = (ks0 & 3) << 3;
    const int vr1 = ks1 >> 2,  vc1 = (ks1 & 3) << 3;

    const uint32_t kd0 = sb + AKh + (kr0 * QPH + kc0) * 2;
    const uint32_t kd1 = sb + AKh + (kr1 * QPH + kc1) * 2;
    const uint32_t vd0 = sb + AVh + (vr0 * VPH + vc0) * 2;
    const uint32_t vd1 = sb + AVh + (vr1 * VPH + vc1) * 2;

    // ---- prologue: tile 0 of this half (cp.async) + shared Q tile ----
    cpa16(kd0, kg + (size_t)kr0 * EE + kc0);
    cpa16(kd1, kg + (size_t)kr1 * EE + kc1);
    cpa16(vd0, vg + (size_t)vr0 * SS + vc0);
    cpa16(vd1, vg + (size_t)vr1 * SS + vc1);
    CP_COMMIT();

#pragma unroll
    for (int i = 0; i < 4; i++) {
        int seg = tid + i * 512;
        int r = seg >> 4, c8 = (seg & 15) << 3;
        *(uint4*)&Qs[r * QPH + c8] = *(const uint4*)&qg[r * EE + c8];
    }
    CP_WAIT0();
    __syncthreads();

    float accO[16][4];
#pragma unroll
    for (int ni = 0; ni < 16; ni++)
#pragma unroll
        for (int ci = 0; ci < 4; ci++) accO[ni][ci] = 0.0f;
    float l0 = 0.0f, l1 = 0.0f;

    const float scl = 0.08838834764831845f;  // 1/sqrt(128)
    const int barid = 1 + half;

    const __half* QA = Qs + (16 * hw + g) * QPH + 2 * t;

    for (int kt = 0; kt < 16; kt++) {
        // ---- prefetch this half's tile kt+1 ----
        if (kt < 15) {
            const __half* kgn = kg + (size_t)(kt + 1) * 32 * EE;
            const __half* vgn = vg + (kt + 1) * 32;
            const uint32_t bo = ((kt + 1) & 1);
            cpa16(kd0 + bo * 8704,  kgn + (size_t)kr0 * EE + kc0);
            cpa16(kd1 + bo * 8704,  kgn + (size_t)kr1 * EE + kc1);
            cpa16(vd0 + bo * 10240, vgn + (size_t)vr0 * SS + vc0);
            cpa16(vd1 + bo * 10240, vgn + (size_t)vr1 * SS + vc1);
            CP_COMMIT();
        }

        const __half* KB = Ksh + (kt & 1) * (32 * QPH) + g * QPH + 2 * t;
        const __half* VB = Vsh + (kt & 1) * (128 * VPH) + g * VPH + 2 * t;

        // ---- gemm1: S(16 rows x 32 keys/warp) = Q . K^T over d=128 ----
        float sc[4][4];
#pragma unroll
        for (int ni = 0; ni < 4; ni++)
#pragma unroll
            for (int ci = 0; ci < 4; ci++) sc[ni][ci] = 0.0f;

#pragma unroll
        for (int k0 = 0; k0 < 8; k0++) {
            uint32_t af[4];
            {
                const __half* p = QA + k0 * 16;
                af[0] = ldh2(p);
                af[1] = ldh2(p + 8 * QPH);
                af[2] = ldh2(p + 8);
                af[3] = ldh2(p + 8 * QPH + 8);
            }
#pragma unroll
            for (int ni = 0; ni < 4; ni++) {
                const __half* p = KB + ni * 8 * QPH + k0 * 16;
                uint32_t bf[2] = {ldh2(p), ldh2(p + 8)};
                mma16(sc[ni], af, bf);
            }
        }

        // ---- softmax numerator in registers; pack as gemm2 A frags ----
        uint32_t pa[2][4];
#pragma unroll
        for (int ni = 0; ni < 4; ni++) {
            float p0 = __expf(sc[ni][0] * scl);
            float p1 = __expf(sc[ni][1] * scl);
            float p2 = __expf(sc[ni][2] * scl);
            float p3 = __expf(sc[ni][3] * scl);
            l0 += p0 + p1;
            l1 += p2 + p3;
            __half2 hA = __floats2half2_rn(p0, p1);
            __half2 hB = __floats2half2_rn(p2, p3);
            const int kg2 = ni >> 1, pos = ni & 1;
            pa[kg2][2 * pos + 0] = *(uint32_t*)&hA;
            pa[kg2][2 * pos + 1] = *(uint32_t*)&hB;
        }

        // ---- gemm2: O(16 x 128/warp) += P . V over these 32 keys ----
#pragma unroll
        for (int kg2 = 0; kg2 < 2; kg2++) {
#pragma unroll
            for (int ni = 0; ni < 16; ni++) {
                const __half* p = VB + ni * 8 * VPH + kg2 * 16;
                uint32_t bf[2] = {ldh2(p), ldh2(p + 8)};
                mma16(accO[ni], pa[kg2], bf);
            }
        }

        CP_WAIT0();
        BAR_HALF(barid);     // syncs only this half's 256 threads
    }

    // ---- quad-reduce this half's row sums ----
    l0 += __shfl_xor_sync(0xffffffffu, l0, 1);
    l0 += __shfl_xor_sync(0xffffffffu, l0, 2);
    l1 += __shfl_xor_sync(0xffffffffu, l1, 1);
    l1 += __shfl_xor_sync(0xffffffffu, l1, 2);

    // ---- combine halves through smem (K/V buffers dead after full sync) ----
    __syncthreads();
    float* Sf = (float*)(smraw + AK_OFF);              // [128][CPIT]
    float* Sl = (float*)(smraw + AK_OFF + 128 * CPIT * 4);   // [128]
    const int r0 = 16 * hw + g;

    if (half == 1) {
#pragma unroll
        for (int ni = 0; ni < 16; ni++) {
            int col = ni * 8 + 2 * t;
            *(float2*)&Sf[r0 * CPIT + col] =
                make_float2(accO[ni][0], accO[ni][1]);
            *(float2*)&Sf[(r0 + 8) * CPIT + col] =
                make_float2(accO[ni][2], accO[ni][3]);
        }
        if (t == 0) { Sl[r0] = l0; Sl[r0 + 8] = l1; }
    }
    __syncthreads();

    if (half == 0) {
        const float inv0 = 1.0f / (l0 + Sl[r0]);
        const float inv1 = 1.0f / (l1 + Sl[r0 + 8]);
        const int b = bh >> 4, h = bh & 15;
        size_t ob0 = (((size_t)b * SS + qt * 128 + r0) * HH + h) * EE;
        size_t ob1 = (((size_t)b * SS + qt * 128 + r0 + 8) * HH + h) * EE;
#pragma unroll
        for (int ni = 0; ni < 16; ni++) {
            int col = ni * 8 + 2 * t;
            float2 c0 = *(float2*)&Sf[r0 * CPIT + col];
            float2 c1 = *(float2*)&Sf[(r0 + 8) * CPIT + col];
            *(float2*)&out[ob0 + col] =
                make_float2((accO[ni][0] + c0.x) * inv0,
                            (accO[ni][1] + c0.y) * inv0);
            *(float2*)&out[ob1 + col] =
                make_float2((accO[ni][2] + c1.x) * inv1,
                            (accO[ni][3] + c1.y) * inv1);
        }
    }
}

// ===========================================================================
extern "C" void kernel_launch(void* const* d_in, const int* in_sizes, int n_in,
                              void* d_out, int out_size)
{
    (void)in_sizes; (void)n_in; (void)out_size;
    const float* X    = (const float*)d_in[0];
    const float* W    = (const float*)d_in[1];
    const float* bias = (const float*)d_in[2];
    float* out = (float*)d_out;

    const int qkv_smem  = 2 * 128 * QPH * (int)sizeof(__half);   // 69632
    const int attn_smem = ATTN_SMEM;                             // 110592

    cudaFuncSetAttribute(qkv_kernel,
                         cudaFuncAttributeMaxDynamicSharedMemorySize, qkv_smem);
    cudaFuncSetAttribute(attn_kernel,
                         cudaFuncAttributeMaxDynamicSharedMemorySize, attn_smem);

    rope_table_kernel<<<(SS * 64 + 511) / 512, 512>>>();
    qkv_kernel<<<dim3(FF / 128, (BB * SS) / 128), 256, qkv_smem>>>(X, W, bias);
    attn_kernel<<<dim3(SS / 128, BHN), 512, attn_smem>>>(out);
}